// round 11
// baseline (speedup 1.0000x reference)
#include <cuda_runtime.h>
#include <cuda.h>
#include <cstdint>

// ============================================================================
// Problem constants  (R9 geometry + dedicated TMA producer warp)
// ============================================================================
#define M_DIM 8192
#define N_DIM 4096
#define K_DIM 4096
#define BM 128
#define BN 256
#define BK 64             // f16 elements per stage = 128 bytes per row
#define STAGES 4
#define NCONS 8           // consumer warps (2 M x 4 N, 64x64 warp tile)
#define NTHREADS 288      // 8 consumer warps + 1 producer warp
#define KIT (K_DIM / BK)  // 64

// Stage = A tile [128 rows][128 B] + B tile [256 rows][128 B]
#define A_TILE_BYTES (BM * 128)                     // 16384
#define B_TILE_BYTES (BN * 128)                     // 32768
#define STAGE_BYTES  (A_TILE_BYTES + B_TILE_BYTES)  // 49152
#define SOFF_FULL  0
#define SOFF_EMPTY 64
#define SOFF_TILE  1024
#define SMEM_TOTAL (SOFF_TILE + STAGES * STAGE_BYTES)  // 197632

// Quant geometry: fused kernel, 4 float4 per thread, 256 thr/block
#define QX_BLOCKS ((M_DIM * K_DIM / 4) / 1024)   // 8192
#define QW_BLOCKS ((N_DIM * K_DIM / 4) / 1024)   // 4096

// f16 scratch (device globals: allocation-free contract); stored as u32 pairs
__device__ __align__(1024) uint32_t g_qx[(size_t)M_DIM * K_DIM / 2];
__device__ __align__(1024) uint32_t g_qw[(size_t)N_DIM * K_DIM / 2];

// ============================================================================
// PTX helpers (baseline sm_90/sm_89 features only — NO tcgen05; harness PTX
// target is compute_103 (no 'a'), which rejects arch-specific instructions)
// ============================================================================
__device__ __forceinline__ uint32_t smem_u32(const void* p) {
    uint32_t a;
    asm("{ .reg .u64 t; cvta.to.shared.u64 t, %1; cvt.u32.u64 %0, t; }"
        : "=r"(a) : "l"(p));
    return a;
}

#define MBARRIER_INIT(addr, count) \
    asm volatile("mbarrier.init.shared.b64 [%0], %1;" \
                 :: "r"((uint32_t)(addr)), "r"((uint32_t)(count)) : "memory")

#define MBARRIER_EXPECT_TX(addr, bytes) \
    asm volatile("mbarrier.arrive.expect_tx.shared.b64 _, [%0], %1;" \
                 :: "r"((uint32_t)(addr)), "r"((uint32_t)(bytes)) : "memory")

#define MBARRIER_ARRIVE(addr) \
    asm volatile("mbarrier.arrive.shared.b64 _, [%0];" \
                 :: "r"((uint32_t)(addr)) : "memory")

#define MBARRIER_WAIT_PARITY(addr, parity) do { \
    uint32_t _m = (uint32_t)(addr); uint32_t _p = (uint32_t)(parity); uint32_t _d; \
    asm volatile("{\n\t.reg .pred p;\n\t" \
        "mbarrier.try_wait.parity.acquire.cta.shared::cta.b64 p, [%1], %2;\n\t" \
        "selp.b32 %0, 1, 0, p;\n\t}" : "=r"(_d) : "r"(_m), "r"(_p) : "memory"); \
    if (!_d) { \
        asm volatile("{\n\t.reg .pred P1;\n\t" \
            "WL_%=:\n\t" \
            "mbarrier.try_wait.parity.acquire.cta.shared::cta.b64 P1, [%0], %1, 0x989680;\n\t" \
            "@P1 bra.uni WD_%=;\n\t" \
            "bra.uni WL_%=;\n\t" \
            "WD_%=:\n\t}" :: "r"(_m), "r"(_p) : "memory"); \
    } \
} while (0)

#define TMA_LOAD_2D(smem_addr, tmap_ptr, cx, cy, mbar) \
    asm volatile( \
        "cp.async.bulk.tensor.2d.shared::cta.global.tile.mbarrier::complete_tx::bytes " \
        "[%0], [%1, {%2, %3}], [%4];" \
        :: "r"((uint32_t)(smem_addr)), "l"(tmap_ptr), \
           "r"((int32_t)(cx)), "r"((int32_t)(cy)), "r"((uint32_t)(mbar)) : "memory")

__device__ __forceinline__ uint32_t lds32(uint32_t a) {
    uint32_t v;
    asm volatile("ld.shared.b32 %0, [%1];" : "=r"(v) : "r"(a));
    return v;
}

// f16 x f16 -> f32 mma, in-place accumulate
__device__ __forceinline__ void mma_f16(float* d, const uint32_t* a,
                                        const uint32_t* b) {
    asm volatile(
        "mma.sync.aligned.m16n8k16.row.col.f32.f16.f16.f32 "
        "{%0,%1,%2,%3}, {%4,%5,%6,%7}, {%8,%9}, {%0,%1,%2,%3};"
        : "+f"(d[0]), "+f"(d[1]), "+f"(d[2]), "+f"(d[3])
        : "r"(a[0]), "r"(a[1]), "r"(a[2]), "r"(a[3]), "r"(b[0]), "r"(b[1]));
}

// ============================================================================
// Kernel 1: fused quantization for BOTH tensors -> f16 values ON the e4m3 grid.
//   Bit-exact vs reference: IEEE f32 div by scale, saturating rn cast to e4m3
//   (the quantization), then EXACT e4m3 -> f16 widening (4-bit mantissa fits).
//   Weight blocks skip the division (scale 1.0, already on grid). MLP=4.
// ============================================================================
__global__ void __launch_bounds__(256) quant_fused_kernel(
        const float4* __restrict__ x,
        const float4* __restrict__ w,
        uint32_t* __restrict__ qx,
        uint32_t* __restrict__ qw,
        const float* __restrict__ in_scale) {
    const int b = blockIdx.x;
    const bool is_x = (b < QX_BLOCKS);
    const float4* __restrict__ src = is_x ? x : w;
    uint32_t* __restrict__ dst = is_x ? qx : qw;
    const int base = (is_x ? b : (b - QX_BLOCKS)) * 1024 + threadIdx.x;
    const float s = is_x ? __ldg(in_scale) : 1.0f;

    float4 v[4];
    #pragma unroll
    for (int j = 0; j < 4; j++) v[j] = src[base + j * 256];  // MLP=4

    #pragma unroll
    for (int j = 0; j < 4; j++) {
        float a, bb, c, d;
        if (is_x) {
            a  = __fdiv_rn(v[j].x, s);
            bb = __fdiv_rn(v[j].y, s);
            c  = __fdiv_rn(v[j].z, s);
            d  = __fdiv_rn(v[j].w, s);
        } else {  // scale == 1.0 -> identity
            a = v[j].x; bb = v[j].y; c = v[j].z; d = v[j].w;
        }
        uint16_t lo8, hi8;
        // cvt d, a, b: d[7:0]=cvt(b), d[15:8]=cvt(a) -> byte0 = element 0
        asm("cvt.rn.satfinite.e4m3x2.f32 %0, %1, %2;" : "=h"(lo8) : "f"(bb), "f"(a));
        asm("cvt.rn.satfinite.e4m3x2.f32 %0, %1, %2;" : "=h"(hi8) : "f"(d),  "f"(c));
        uint32_t lo16, hi16;  // exact widening e4m3 -> f16 (half0 = byte0)
        asm("cvt.rn.f16x2.e4m3x2 %0, %1;" : "=r"(lo16) : "h"(lo8));
        asm("cvt.rn.f16x2.e4m3x2 %0, %1;" : "=r"(hi16) : "h"(hi8));
        uint2 o; o.x = lo16; o.y = hi16;
        *reinterpret_cast<uint2*>(dst + 2 * (base + j * 256)) = o;
    }
}

// ============================================================================
// Kernel 2: warp-specialized multistage f16 mma.sync GEMM.
//   out[128,256] tile = qx[128,K] @ qw[256,K]^T  (both K-major f16)
//   Warps 0-7: pure consumers (full-wait -> mma burst -> empty-arrive).
//   Warp 8 lane 0: dedicated TMA producer (empty-wait -> expect_tx -> TMA).
//   This removes the R8/R9 producer convoy where warp 0's empty-wait chained
//   it to the slowest warp every iteration (held tensor at 84%).
// ============================================================================
__global__ void __launch_bounds__(NTHREADS, 1)
f16_gemm_kernel(const __grid_constant__ CUtensorMap tmA,
                const __grid_constant__ CUtensorMap tmB,
                const float* __restrict__ bias,
                const float* __restrict__ in_scale,
                const float* __restrict__ w_scale,
                float* __restrict__ out) {
    extern __shared__ __align__(1024) unsigned char smem[];
    const uint32_t sbase = smem_u32(smem);
    const int tid = threadIdx.x;
    const int wid = tid >> 5;
    const int lane = tid & 31;
    const int m0 = blockIdx.y * BM;
    const int n0 = blockIdx.x * BN;

    if (tid == 0) {
        #pragma unroll
        for (int s = 0; s < STAGES; s++) {
            MBARRIER_INIT(sbase + SOFF_FULL + 8 * s, 1);
            MBARRIER_INIT(sbase + SOFF_EMPTY + 8 * s, NCONS);
        }
    }
    __syncthreads();  // barriers visible before any wait / TMA

    // ---------------- producer warp ----------------
    if (wid == NCONS) {
        if (lane == 0) {
            int s = 0, php = 1;  // flipped initial parity: first ring passes
            for (int it = 0; it < KIT; ++it) {
                MBARRIER_WAIT_PARITY(sbase + SOFF_EMPTY + 8 * s, php);
                uint32_t full = sbase + SOFF_FULL + 8 * s;
                MBARRIER_EXPECT_TX(full, STAGE_BYTES);
                uint32_t st = sbase + SOFF_TILE + s * STAGE_BYTES;
                int k0 = it * BK;
                TMA_LOAD_2D(st,                &tmA, k0, m0, full);
                TMA_LOAD_2D(st + A_TILE_BYTES, &tmB, k0, n0, full);
                if (++s == STAGES) { s = 0; php ^= 1; }
            }
        }
        return;  // producer warp done
    }

    // ---------------- consumer warps (0..7) ----------------
    const int gid = lane >> 2;   // group id 0..7 (fragment row-in-8)
    const int tig = lane & 3;    // thread-in-group
    const int warp_m = (wid & 1) * 64;    // 2 warps along M
    const int warp_n = (wid >> 1) * 64;   // 4 warps along N

    // SW128 swizzle term for our rows is ((row&7)<<4) = gid<<4, constant per
    // thread. k16 step = 32 bytes.
    const uint32_t sx = (uint32_t)gid << 4;
    uint32_t co[4][2];
    #pragma unroll
    for (int s4 = 0; s4 < 4; s4++) {
        #pragma unroll
        for (int h = 0; h < 2; h++)
            co[s4][h] = ((uint32_t)(s4 * 32 + h * 16 + tig * 4)) ^ sx;
    }
    const uint32_t baseA0 = (uint32_t)(warp_m + gid) * 128;
    const uint32_t baseB0 = (uint32_t)(warp_n + gid) * 128 + A_TILE_BYTES;

    float acc[4][8][4];   // 128 f32 accumulators, direct mma accumulation
    #pragma unroll
    for (int i = 0; i < 4; i++)
        #pragma unroll
        for (int j = 0; j < 8; j++)
            #pragma unroll
            for (int q = 0; q < 4; q++) acc[i][j][q] = 0.f;

    int s = 0, ph = 0;   // ph = (it/STAGES)&1, tracked incrementally
    for (int it = 0; it < KIT; ++it) {
        MBARRIER_WAIT_PARITY(sbase + SOFF_FULL + 8 * s, ph);

        const uint32_t stg = sbase + SOFF_TILE + (uint32_t)s * STAGE_BYTES;
        const uint32_t aBase = stg + baseA0;
        const uint32_t bBase = stg + baseB0;
        #pragma unroll
        for (int s4 = 0; s4 < 4; s4++) {  // 4 x k16 per BK=64 stage
            uint32_t Af[4][4];
            #pragma unroll
            for (int fm = 0; fm < 4; fm++) {
                const uint32_t a0 = aBase + fm * 2048 + co[s4][0];
                const uint32_t a1 = aBase + fm * 2048 + co[s4][1];
                Af[fm][0] = lds32(a0);
                Af[fm][1] = lds32(a0 + 1024);
                Af[fm][2] = lds32(a1);
                Af[fm][3] = lds32(a1 + 1024);
            }
            uint32_t Bf[8][2];
            #pragma unroll
            for (int fn = 0; fn < 8; fn++) {
                const uint32_t b0 = bBase + fn * 1024;
                Bf[fn][0] = lds32(b0 + co[s4][0]);
                Bf[fn][1] = lds32(b0 + co[s4][1]);
            }
            #pragma unroll
            for (int fn = 0; fn < 8; fn++)
                #pragma unroll
                for (int fm = 0; fm < 4; fm++)
                    mma_f16(acc[fm][fn], Af[fm], Bf[fn]);
        }

        // This warp is done reading stage s.
        if (lane == 0) MBARRIER_ARRIVE(sbase + SOFF_EMPTY + 8 * s);

        if (++s == STAGES) { s = 0; ph ^= 1; }
    }

    // Epilogue: scale + bias, float2 stores
    const float sc = __ldg(in_scale) * __ldg(w_scale);
    #pragma unroll
    for (int fm = 0; fm < 4; fm++) {
        const int r0 = m0 + warp_m + fm * 16 + gid;
        #pragma unroll
        for (int fn = 0; fn < 8; fn++) {
            const int col = n0 + warp_n + fn * 8 + 2 * tig;
            const float2 bv = *reinterpret_cast<const float2*>(bias + col);
            float2 o0, o1;
            o0.x = fmaf(acc[fm][fn][0], sc, bv.x);
            o0.y = fmaf(acc[fm][fn][1], sc, bv.y);
            o1.x = fmaf(acc[fm][fn][2], sc, bv.x);
            o1.y = fmaf(acc[fm][fn][3], sc, bv.y);
            *reinterpret_cast<float2*>(out + (size_t)r0 * N_DIM + col) = o0;
            *reinterpret_cast<float2*>(out + (size_t)(r0 + 8) * N_DIM + col) = o1;
        }
    }
}

// ============================================================================
// Host launch
// ============================================================================
typedef CUresult (CUDAAPI* PFN_encodeTiled)(
    CUtensorMap*, CUtensorMapDataType, cuuint32_t, void*,
    const cuuint64_t*, const cuuint64_t*, const cuuint32_t*, const cuuint32_t*,
    CUtensorMapInterleave, CUtensorMapSwizzle, CUtensorMapL2promotion,
    CUtensorMapFloatOOBfill);

extern "C" void kernel_launch(void* const* d_in, const int* in_sizes, int n_in,
                              void* d_out, int out_size) {
    const float* x      = (const float*)d_in[0];
    const float* w      = (const float*)d_in[1];
    const float* wscale = (const float*)d_in[2];
    const float* bias   = (const float*)d_in[3];
    const float* iscale = (const float*)d_in[4];
    float* out = (float*)d_out;
    (void)in_sizes; (void)n_in; (void)out_size;

    void* qx_p = nullptr; void* qw_p = nullptr;
    cudaGetSymbolAddress(&qx_p, g_qx);
    cudaGetSymbolAddress(&qw_p, g_qw);

    // --- fused quantization to f16-on-e4m3-grid ---
    quant_fused_kernel<<<QX_BLOCKS + QW_BLOCKS, 256>>>(
        (const float4*)x, (const float4*)w,
        (uint32_t*)qx_p, (uint32_t*)qw_p, iscale);

    // --- TMA descriptors (driver entry point via cudart; no -lcuda needed) ---
    PFN_encodeTiled encode = nullptr;
    cudaDriverEntryPointQueryResult qr;
    cudaGetDriverEntryPoint("cuTensorMapEncodeTiled", (void**)&encode,
                            cudaEnableDefault, &qr);

    CUtensorMap tmA, tmB;
    {
        cuuint64_t dims[2]    = {K_DIM, M_DIM};       // elems
        cuuint64_t strides[1] = {K_DIM * 2};          // bytes
        cuuint32_t box[2]     = {BK, BM};             // 64 f16 = 128B (SW128)
        cuuint32_t es[2]      = {1, 1};
        encode(&tmA, CU_TENSOR_MAP_DATA_TYPE_FLOAT16, 2, qx_p, dims, strides,
               box, es, CU_TENSOR_MAP_INTERLEAVE_NONE, CU_TENSOR_MAP_SWIZZLE_128B,
               CU_TENSOR_MAP_L2_PROMOTION_L2_128B, CU_TENSOR_MAP_FLOAT_OOB_FILL_NONE);
    }
    {
        cuuint64_t dims[2]    = {K_DIM, N_DIM};
        cuuint64_t strides[1] = {K_DIM * 2};
        cuuint32_t box[2]     = {BK, BN};             // 64 x 256 box
        cuuint32_t es[2]      = {1, 1};
        encode(&tmB, CU_TENSOR_MAP_DATA_TYPE_FLOAT16, 2, qw_p, dims, strides,
               box, es, CU_TENSOR_MAP_INTERLEAVE_NONE, CU_TENSOR_MAP_SWIZZLE_128B,
               CU_TENSOR_MAP_L2_PROMOTION_L2_128B, CU_TENSOR_MAP_FLOAT_OOB_FILL_NONE);
    }

    cudaFuncSetAttribute(f16_gemm_kernel,
                         cudaFuncAttributeMaxDynamicSharedMemorySize, SMEM_TOTAL);
    dim3 grid(N_DIM / BN, M_DIM / BM);  // (16, 64) = 1024 CTAs
    f16_gemm_kernel<<<grid, NTHREADS, SMEM_TOTAL>>>(
        tmA, tmB, bias, iscale, wscale, out);
}

// round 12
// speedup vs baseline: 1.0898x; 1.0898x over previous
#include <cuda_runtime.h>
#include <cuda.h>
#include <cstdint>

// ============================================================================
// Problem constants  (R10 geometry + distributed stage ownership)
// ============================================================================
#define M_DIM 8192
#define N_DIM 4096
#define K_DIM 4096
#define BM 128
#define BN 256
#define BK 64             // f16 elements per stage = 128 bytes per row
#define STAGES 4
#define NTHREADS 256
#define NWARPS (NTHREADS / 32)
#define KIT (K_DIM / BK)  // 64

// Stage = A tile [128 rows][128 B] + B tile [256 rows][128 B]
#define A_TILE_BYTES (BM * 128)                     // 16384
#define B_TILE_BYTES (BN * 128)                     // 32768
#define STAGE_BYTES  (A_TILE_BYTES + B_TILE_BYTES)  // 49152
#define SOFF_FULL  0
#define SOFF_EMPTY 64
#define SOFF_TILE  1024
#define SMEM_TOTAL (SOFF_TILE + STAGES * STAGE_BYTES)  // 197632

// Quant geometry: fused kernel, 4 float4 per thread, 256 thr/block
#define QX_BLOCKS ((M_DIM * K_DIM / 4) / 1024)   // 8192
#define QW_BLOCKS ((N_DIM * K_DIM / 4) / 1024)   // 4096

// f16 scratch (device globals: allocation-free contract); stored as u32 pairs
__device__ __align__(1024) uint32_t g_qx[(size_t)M_DIM * K_DIM / 2];
__device__ __align__(1024) uint32_t g_qw[(size_t)N_DIM * K_DIM / 2];

// ============================================================================
// PTX helpers (baseline sm_90/sm_89 features only — NO tcgen05; harness PTX
// target is compute_103 (no 'a'), which rejects arch-specific instructions)
// ============================================================================
__device__ __forceinline__ uint32_t smem_u32(const void* p) {
    uint32_t a;
    asm("{ .reg .u64 t; cvta.to.shared.u64 t, %1; cvt.u32.u64 %0, t; }"
        : "=r"(a) : "l"(p));
    return a;
}

#define MBARRIER_INIT(addr, count) \
    asm volatile("mbarrier.init.shared.b64 [%0], %1;" \
                 :: "r"((uint32_t)(addr)), "r"((uint32_t)(count)) : "memory")

#define MBARRIER_EXPECT_TX(addr, bytes) \
    asm volatile("mbarrier.arrive.expect_tx.shared.b64 _, [%0], %1;" \
                 :: "r"((uint32_t)(addr)), "r"((uint32_t)(bytes)) : "memory")

#define MBARRIER_ARRIVE(addr) \
    asm volatile("mbarrier.arrive.shared.b64 _, [%0];" \
                 :: "r"((uint32_t)(addr)) : "memory")

#define MBARRIER_WAIT_PARITY(addr, parity) do { \
    uint32_t _m = (uint32_t)(addr); uint32_t _p = (uint32_t)(parity); uint32_t _d; \
    asm volatile("{\n\t.reg .pred p;\n\t" \
        "mbarrier.try_wait.parity.acquire.cta.shared::cta.b64 p, [%1], %2;\n\t" \
        "selp.b32 %0, 1, 0, p;\n\t}" : "=r"(_d) : "r"(_m), "r"(_p) : "memory"); \
    if (!_d) { \
        asm volatile("{\n\t.reg .pred P1;\n\t" \
            "WL_%=:\n\t" \
            "mbarrier.try_wait.parity.acquire.cta.shared::cta.b64 P1, [%0], %1, 0x989680;\n\t" \
            "@P1 bra.uni WD_%=;\n\t" \
            "bra.uni WL_%=;\n\t" \
            "WD_%=:\n\t}" :: "r"(_m), "r"(_p) : "memory"); \
    } \
} while (0)

#define TMA_LOAD_2D(smem_addr, tmap_ptr, cx, cy, mbar) \
    asm volatile( \
        "cp.async.bulk.tensor.2d.shared::cta.global.tile.mbarrier::complete_tx::bytes " \
        "[%0], [%1, {%2, %3}], [%4];" \
        :: "r"((uint32_t)(smem_addr)), "l"(tmap_ptr), \
           "r"((int32_t)(cx)), "r"((int32_t)(cy)), "r"((uint32_t)(mbar)) : "memory")

__device__ __forceinline__ uint32_t lds32(uint32_t a) {
    uint32_t v;
    asm volatile("ld.shared.b32 %0, [%1];" : "=r"(v) : "r"(a));
    return v;
}

// f16 x f16 -> f32 mma, in-place accumulate
__device__ __forceinline__ void mma_f16(float* d, const uint32_t* a,
                                        const uint32_t* b) {
    asm volatile(
        "mma.sync.aligned.m16n8k16.row.col.f32.f16.f16.f32 "
        "{%0,%1,%2,%3}, {%4,%5,%6,%7}, {%8,%9}, {%0,%1,%2,%3};"
        : "+f"(d[0]), "+f"(d[1]), "+f"(d[2]), "+f"(d[3])
        : "r"(a[0]), "r"(a[1]), "r"(a[2]), "r"(a[3]), "r"(b[0]), "r"(b[1]));
}

// ============================================================================
// Kernel 1: fused quantization for BOTH tensors -> f16 values ON the e4m3 grid.
//   Bit-exact vs reference: IEEE f32 div by scale, saturating rn cast to e4m3
//   (the quantization), then EXACT e4m3 -> f16 widening (4-bit mantissa fits).
//   Weight blocks skip the division (scale 1.0, already on grid). MLP=4.
// ============================================================================
__global__ void __launch_bounds__(256) quant_fused_kernel(
        const float4* __restrict__ x,
        const float4* __restrict__ w,
        uint32_t* __restrict__ qx,
        uint32_t* __restrict__ qw,
        const float* __restrict__ in_scale) {
    const int b = blockIdx.x;
    const bool is_x = (b < QX_BLOCKS);
    const float4* __restrict__ src = is_x ? x : w;
    uint32_t* __restrict__ dst = is_x ? qx : qw;
    const int base = (is_x ? b : (b - QX_BLOCKS)) * 1024 + threadIdx.x;
    const float s = is_x ? __ldg(in_scale) : 1.0f;

    float4 v[4];
    #pragma unroll
    for (int j = 0; j < 4; j++) v[j] = src[base + j * 256];  // MLP=4

    #pragma unroll
    for (int j = 0; j < 4; j++) {
        float a, bb, c, d;
        if (is_x) {
            a  = __fdiv_rn(v[j].x, s);
            bb = __fdiv_rn(v[j].y, s);
            c  = __fdiv_rn(v[j].z, s);
            d  = __fdiv_rn(v[j].w, s);
        } else {  // scale == 1.0 -> identity
            a = v[j].x; bb = v[j].y; c = v[j].z; d = v[j].w;
        }
        uint16_t lo8, hi8;
        // cvt d, a, b: d[7:0]=cvt(b), d[15:8]=cvt(a) -> byte0 = element 0
        asm("cvt.rn.satfinite.e4m3x2.f32 %0, %1, %2;" : "=h"(lo8) : "f"(bb), "f"(a));
        asm("cvt.rn.satfinite.e4m3x2.f32 %0, %1, %2;" : "=h"(hi8) : "f"(d),  "f"(c));
        uint32_t lo16, hi16;  // exact widening e4m3 -> f16 (half0 = byte0)
        asm("cvt.rn.f16x2.e4m3x2 %0, %1;" : "=r"(lo16) : "h"(lo8));
        asm("cvt.rn.f16x2.e4m3x2 %0, %1;" : "=r"(hi16) : "h"(hi8));
        uint2 o; o.x = lo16; o.y = hi16;
        *reinterpret_cast<uint2*>(dst + 2 * (base + j * 256)) = o;
    }
}

// ============================================================================
// Kernel 2: multistage f16 mma.sync GEMM, empty-ring pipelined, 64x64 warp
// tile, DISTRIBUTED stage ownership: stage s in ring round ph is refilled by
// warp (s + 4*ph), so each warp takes the convoy-inducing empty-wait only
// once per 8 iterations (R9 had warp 0 take it every iteration; R11's extra
// producer warp broke SMSP balance).
//   out[128,256] tile = qx[128,K] @ qw[256,K]^T  (both K-major f16)
//   8 warps (2 M x 4 N); 4-stage TMA ring, 48 KB/stage.
// ============================================================================
__device__ __forceinline__ void issue_stage(uint32_t sbase, int it, int m0,
                                            int n0, const CUtensorMap* tA,
                                            const CUtensorMap* tB) {
    int s = it % STAGES;
    uint32_t full = sbase + SOFF_FULL + 8 * s;
    MBARRIER_EXPECT_TX(full, STAGE_BYTES);
    uint32_t st = sbase + SOFF_TILE + s * STAGE_BYTES;
    int k0 = it * BK;  // element coords
    TMA_LOAD_2D(st,                tA, k0, m0, full);
    TMA_LOAD_2D(st + A_TILE_BYTES, tB, k0, n0, full);
}

__global__ void __launch_bounds__(NTHREADS, 1)
f16_gemm_kernel(const __grid_constant__ CUtensorMap tmA,
                const __grid_constant__ CUtensorMap tmB,
                const float* __restrict__ bias,
                const float* __restrict__ in_scale,
                const float* __restrict__ w_scale,
                float* __restrict__ out) {
    extern __shared__ __align__(1024) unsigned char smem[];
    const uint32_t sbase = smem_u32(smem);
    const int tid = threadIdx.x;
    const int wid = tid >> 5;
    const int lane = tid & 31;
    const int gid = lane >> 2;   // group id 0..7 (fragment row-in-8)
    const int tig = lane & 3;    // thread-in-group
    const int warp_m = (wid & 1) * 64;    // 2 warps along M
    const int warp_n = (wid >> 1) * 64;   // 4 warps along N
    const int m0 = blockIdx.y * BM;
    const int n0 = blockIdx.x * BN;

    if (tid == 0) {
        #pragma unroll
        for (int s = 0; s < STAGES; s++) {
            MBARRIER_INIT(sbase + SOFF_FULL + 8 * s, 1);
            MBARRIER_INIT(sbase + SOFF_EMPTY + 8 * s, NWARPS);
        }
    }
    __syncthreads();  // barriers visible before any wait / TMA

    // Prologue: fill the whole ring (depth STAGES)
    if (tid == 0) {
        issue_stage(sbase, 0, m0, n0, &tmA, &tmB);
        issue_stage(sbase, 1, m0, n0, &tmA, &tmB);
        issue_stage(sbase, 2, m0, n0, &tmA, &tmB);
        issue_stage(sbase, 3, m0, n0, &tmA, &tmB);
    }

    // SW128 swizzle term for our rows is ((row&7)<<4) = gid<<4, constant per
    // thread. k16 step = 32 bytes.
    const uint32_t sx = (uint32_t)gid << 4;
    uint32_t co[4][2];
    #pragma unroll
    for (int s4 = 0; s4 < 4; s4++) {
        #pragma unroll
        for (int h = 0; h < 2; h++)
            co[s4][h] = ((uint32_t)(s4 * 32 + h * 16 + tig * 4)) ^ sx;
    }
    const uint32_t baseA0 = (uint32_t)(warp_m + gid) * 128;
    const uint32_t baseB0 = (uint32_t)(warp_n + gid) * 128 + A_TILE_BYTES;

    float acc[4][8][4];   // 128 f32 accumulators, direct mma accumulation
    #pragma unroll
    for (int i = 0; i < 4; i++)
        #pragma unroll
        for (int j = 0; j < 8; j++)
            #pragma unroll
            for (int q = 0; q < 4; q++) acc[i][j][q] = 0.f;

    int s = 0, ph = 0;   // ph = (it/STAGES)&1, tracked incrementally
    for (int it = 0; it < KIT; ++it) {
        MBARRIER_WAIT_PARITY(sbase + SOFF_FULL + 8 * s, ph);

        const uint32_t stg = sbase + SOFF_TILE + (uint32_t)s * STAGE_BYTES;
        const uint32_t aBase = stg + baseA0;
        const uint32_t bBase = stg + baseB0;
        #pragma unroll
        for (int s4 = 0; s4 < 4; s4++) {  // 4 x k16 per BK=64 stage
            uint32_t Af[4][4];
            #pragma unroll
            for (int fm = 0; fm < 4; fm++) {
                const uint32_t a0 = aBase + fm * 2048 + co[s4][0];
                const uint32_t a1 = aBase + fm * 2048 + co[s4][1];
                Af[fm][0] = lds32(a0);
                Af[fm][1] = lds32(a0 + 1024);
                Af[fm][2] = lds32(a1);
                Af[fm][3] = lds32(a1 + 1024);
            }
            uint32_t Bf[8][2];
            #pragma unroll
            for (int fn = 0; fn < 8; fn++) {
                const uint32_t b0 = bBase + fn * 1024;
                Bf[fn][0] = lds32(b0 + co[s4][0]);
                Bf[fn][1] = lds32(b0 + co[s4][1]);
            }
            #pragma unroll
            for (int fn = 0; fn < 8; fn++)
                #pragma unroll
                for (int fm = 0; fm < 4; fm++)
                    mma_f16(acc[fm][fn], Af[fm], Bf[fn]);
        }

        // This warp is done reading stage s.
        if (lane == 0) MBARRIER_ARRIVE(sbase + SOFF_EMPTY + 8 * s);

        // Distributed producer: warp (s + 4*ph) owns the refill of stage s
        // this round. Only that warp takes the empty-wait (chained to the
        // slowest consumer); every other warp drifts freely in ring slack.
        if (wid == s + (ph << 2) && lane == 0 && it + STAGES < KIT) {
            MBARRIER_WAIT_PARITY(sbase + SOFF_EMPTY + 8 * s, ph);
            issue_stage(sbase, it + STAGES, m0, n0, &tmA, &tmB);
        }

        if (++s == STAGES) { s = 0; ph ^= 1; }
    }

    // Epilogue: scale + bias, float2 stores
    const float sc = __ldg(in_scale) * __ldg(w_scale);
    #pragma unroll
    for (int fm = 0; fm < 4; fm++) {
        const int r0 = m0 + warp_m + fm * 16 + gid;
        #pragma unroll
        for (int fn = 0; fn < 8; fn++) {
            const int col = n0 + warp_n + fn * 8 + 2 * tig;
            const float2 bv = *reinterpret_cast<const float2*>(bias + col);
            float2 o0, o1;
            o0.x = fmaf(acc[fm][fn][0], sc, bv.x);
            o0.y = fmaf(acc[fm][fn][1], sc, bv.y);
            o1.x = fmaf(acc[fm][fn][2], sc, bv.x);
            o1.y = fmaf(acc[fm][fn][3], sc, bv.y);
            *reinterpret_cast<float2*>(out + (size_t)r0 * N_DIM + col) = o0;
            *reinterpret_cast<float2*>(out + (size_t)(r0 + 8) * N_DIM + col) = o1;
        }
    }
}

// ============================================================================
// Host launch
// ============================================================================
typedef CUresult (CUDAAPI* PFN_encodeTiled)(
    CUtensorMap*, CUtensorMapDataType, cuuint32_t, void*,
    const cuuint64_t*, const cuuint64_t*, const cuuint32_t*, const cuuint32_t*,
    CUtensorMapInterleave, CUtensorMapSwizzle, CUtensorMapL2promotion,
    CUtensorMapFloatOOBfill);

extern "C" void kernel_launch(void* const* d_in, const int* in_sizes, int n_in,
                              void* d_out, int out_size) {
    const float* x      = (const float*)d_in[0];
    const float* w      = (const float*)d_in[1];
    const float* wscale = (const float*)d_in[2];
    const float* bias   = (const float*)d_in[3];
    const float* iscale = (const float*)d_in[4];
    float* out = (float*)d_out;
    (void)in_sizes; (void)n_in; (void)out_size;

    void* qx_p = nullptr; void* qw_p = nullptr;
    cudaGetSymbolAddress(&qx_p, g_qx);
    cudaGetSymbolAddress(&qw_p, g_qw);

    // --- fused quantization to f16-on-e4m3-grid ---
    quant_fused_kernel<<<QX_BLOCKS + QW_BLOCKS, 256>>>(
        (const float4*)x, (const float4*)w,
        (uint32_t*)qx_p, (uint32_t*)qw_p, iscale);

    // --- TMA descriptors (driver entry point via cudart; no -lcuda needed) ---
    PFN_encodeTiled encode = nullptr;
    cudaDriverEntryPointQueryResult qr;
    cudaGetDriverEntryPoint("cuTensorMapEncodeTiled", (void**)&encode,
                            cudaEnableDefault, &qr);

    CUtensorMap tmA, tmB;
    {
        cuuint64_t dims[2]    = {K_DIM, M_DIM};       // elems
        cuuint64_t strides[1] = {K_DIM * 2};          // bytes
        cuuint32_t box[2]     = {BK, BM};             // 64 f16 = 128B (SW128)
        cuuint32_t es[2]      = {1, 1};
        encode(&tmA, CU_TENSOR_MAP_DATA_TYPE_FLOAT16, 2, qx_p, dims, strides,
               box, es, CU_TENSOR_MAP_INTERLEAVE_NONE, CU_TENSOR_MAP_SWIZZLE_128B,
               CU_TENSOR_MAP_L2_PROMOTION_L2_128B, CU_TENSOR_MAP_FLOAT_OOB_FILL_NONE);
    }
    {
        cuuint64_t dims[2]    = {K_DIM, N_DIM};
        cuuint64_t strides[1] = {K_DIM * 2};
        cuuint32_t box[2]     = {BK, BN};             // 64 x 256 box
        cuuint32_t es[2]      = {1, 1};
        encode(&tmB, CU_TENSOR_MAP_DATA_TYPE_FLOAT16, 2, qw_p, dims, strides,
               box, es, CU_TENSOR_MAP_INTERLEAVE_NONE, CU_TENSOR_MAP_SWIZZLE_128B,
               CU_TENSOR_MAP_L2_PROMOTION_L2_128B, CU_TENSOR_MAP_FLOAT_OOB_FILL_NONE);
    }

    cudaFuncSetAttribute(f16_gemm_kernel,
                         cudaFuncAttributeMaxDynamicSharedMemorySize, SMEM_TOTAL);
    dim3 grid(N_DIM / BN, M_DIM / BM);  // (16, 64) = 1024 CTAs
    f16_gemm_kernel<<<grid, NTHREADS, SMEM_TOTAL>>>(
        tmA, tmB, bias, iscale, wscale, out);
}

// round 13
// speedup vs baseline: 1.1199x; 1.0276x over previous
#include <cuda_runtime.h>
#include <cuda.h>
#include <cstdint>

// ============================================================================
// Problem constants  (R10 pipeline — best measured — made persistent)
// ============================================================================
#define M_DIM 8192
#define N_DIM 4096
#define K_DIM 4096
#define BM 128
#define BN 256
#define BK 64             // f16 elements per stage = 128 bytes per row
#define STAGES 4
#define NTHREADS 256
#define NWARPS (NTHREADS / 32)
#define KIT (K_DIM / BK)  // 64
#define NTILES ((M_DIM / BM) * (N_DIM / BN))  // 64 x 16 = 1024
#define NT_X (N_DIM / BN)                     // 16 n-tiles

// Stage = A tile [128 rows][128 B] + B tile [256 rows][128 B]
#define A_TILE_BYTES (BM * 128)                     // 16384
#define B_TILE_BYTES (BN * 128)                     // 32768
#define STAGE_BYTES  (A_TILE_BYTES + B_TILE_BYTES)  // 49152
#define SOFF_FULL  0
#define SOFF_EMPTY 64
#define SOFF_TILE  1024
#define SMEM_TOTAL (SOFF_TILE + STAGES * STAGE_BYTES)  // 197632

// Quant geometry: fused kernel, 4 float4 per thread, 256 thr/block
#define QX_BLOCKS ((M_DIM * K_DIM / 4) / 1024)   // 8192
#define QW_BLOCKS ((N_DIM * K_DIM / 4) / 1024)   // 4096

// f16 scratch (device globals: allocation-free contract); stored as u32 pairs
__device__ __align__(1024) uint32_t g_qx[(size_t)M_DIM * K_DIM / 2];
__device__ __align__(1024) uint32_t g_qw[(size_t)N_DIM * K_DIM / 2];

// ============================================================================
// PTX helpers (baseline sm_90/sm_89 features only — NO tcgen05; harness PTX
// target is compute_103 (no 'a'), which rejects arch-specific instructions)
// ============================================================================
__device__ __forceinline__ uint32_t smem_u32(const void* p) {
    uint32_t a;
    asm("{ .reg .u64 t; cvta.to.shared.u64 t, %1; cvt.u32.u64 %0, t; }"
        : "=r"(a) : "l"(p));
    return a;
}

#define MBARRIER_INIT(addr, count) \
    asm volatile("mbarrier.init.shared.b64 [%0], %1;" \
                 :: "r"((uint32_t)(addr)), "r"((uint32_t)(count)) : "memory")

#define MBARRIER_EXPECT_TX(addr, bytes) \
    asm volatile("mbarrier.arrive.expect_tx.shared.b64 _, [%0], %1;" \
                 :: "r"((uint32_t)(addr)), "r"((uint32_t)(bytes)) : "memory")

#define MBARRIER_ARRIVE(addr) \
    asm volatile("mbarrier.arrive.shared.b64 _, [%0];" \
                 :: "r"((uint32_t)(addr)) : "memory")

#define MBARRIER_WAIT_PARITY(addr, parity) do { \
    uint32_t _m = (uint32_t)(addr); uint32_t _p = (uint32_t)(parity); uint32_t _d; \
    asm volatile("{\n\t.reg .pred p;\n\t" \
        "mbarrier.try_wait.parity.acquire.cta.shared::cta.b64 p, [%1], %2;\n\t" \
        "selp.b32 %0, 1, 0, p;\n\t}" : "=r"(_d) : "r"(_m), "r"(_p) : "memory"); \
    if (!_d) { \
        asm volatile("{\n\t.reg .pred P1;\n\t" \
            "WL_%=:\n\t" \
            "mbarrier.try_wait.parity.acquire.cta.shared::cta.b64 P1, [%0], %1, 0x989680;\n\t" \
            "@P1 bra.uni WD_%=;\n\t" \
            "bra.uni WL_%=;\n\t" \
            "WD_%=:\n\t}" :: "r"(_m), "r"(_p) : "memory"); \
    } \
} while (0)

#define TMA_LOAD_2D(smem_addr, tmap_ptr, cx, cy, mbar) \
    asm volatile( \
        "cp.async.bulk.tensor.2d.shared::cta.global.tile.mbarrier::complete_tx::bytes " \
        "[%0], [%1, {%2, %3}], [%4];" \
        :: "r"((uint32_t)(smem_addr)), "l"(tmap_ptr), \
           "r"((int32_t)(cx)), "r"((int32_t)(cy)), "r"((uint32_t)(mbar)) : "memory")

__device__ __forceinline__ uint32_t lds32(uint32_t a) {
    uint32_t v;
    asm volatile("ld.shared.b32 %0, [%1];" : "=r"(v) : "r"(a));
    return v;
}

// f16 x f16 -> f32 mma, in-place accumulate
__device__ __forceinline__ void mma_f16(float* d, const uint32_t* a,
                                        const uint32_t* b) {
    asm volatile(
        "mma.sync.aligned.m16n8k16.row.col.f32.f16.f16.f32 "
        "{%0,%1,%2,%3}, {%4,%5,%6,%7}, {%8,%9}, {%0,%1,%2,%3};"
        : "+f"(d[0]), "+f"(d[1]), "+f"(d[2]), "+f"(d[3])
        : "r"(a[0]), "r"(a[1]), "r"(a[2]), "r"(a[3]), "r"(b[0]), "r"(b[1]));
}

// ============================================================================
// Kernel 1: fused quantization for BOTH tensors -> f16 values ON the e4m3 grid.
//   Bit-exact vs reference: IEEE f32 div by scale, saturating rn cast to e4m3
//   (the quantization), then EXACT e4m3 -> f16 widening (4-bit mantissa fits).
//   Weight blocks skip the division (scale 1.0, already on grid). MLP=4.
// ============================================================================
__global__ void __launch_bounds__(256) quant_fused_kernel(
        const float4* __restrict__ x,
        const float4* __restrict__ w,
        uint32_t* __restrict__ qx,
        uint32_t* __restrict__ qw,
        const float* __restrict__ in_scale) {
    const int b = blockIdx.x;
    const bool is_x = (b < QX_BLOCKS);
    const float4* __restrict__ src = is_x ? x : w;
    uint32_t* __restrict__ dst = is_x ? qx : qw;
    const int base = (is_x ? b : (b - QX_BLOCKS)) * 1024 + threadIdx.x;
    const float s = is_x ? __ldg(in_scale) : 1.0f;

    float4 v[4];
    #pragma unroll
    for (int j = 0; j < 4; j++) v[j] = src[base + j * 256];  // MLP=4

    #pragma unroll
    for (int j = 0; j < 4; j++) {
        float a, bb, c, d;
        if (is_x) {
            a  = __fdiv_rn(v[j].x, s);
            bb = __fdiv_rn(v[j].y, s);
            c  = __fdiv_rn(v[j].z, s);
            d  = __fdiv_rn(v[j].w, s);
        } else {  // scale == 1.0 -> identity
            a = v[j].x; bb = v[j].y; c = v[j].z; d = v[j].w;
        }
        uint16_t lo8, hi8;
        // cvt d, a, b: d[7:0]=cvt(b), d[15:8]=cvt(a) -> byte0 = element 0
        asm("cvt.rn.satfinite.e4m3x2.f32 %0, %1, %2;" : "=h"(lo8) : "f"(bb), "f"(a));
        asm("cvt.rn.satfinite.e4m3x2.f32 %0, %1, %2;" : "=h"(hi8) : "f"(d),  "f"(c));
        uint32_t lo16, hi16;  // exact widening e4m3 -> f16 (half0 = byte0)
        asm("cvt.rn.f16x2.e4m3x2 %0, %1;" : "=r"(lo16) : "h"(lo8));
        asm("cvt.rn.f16x2.e4m3x2 %0, %1;" : "=r"(hi16) : "h"(hi8));
        uint2 o; o.x = lo16; o.y = hi16;
        *reinterpret_cast<uint2*>(dst + 2 * (base + j * 256)) = o;
    }
}

// ============================================================================
// Kernel 2: PERSISTENT multistage f16 mma.sync GEMM (R10 pipeline verbatim,
// with a continuous global iteration count across tiles).
//   Each CTA walks tiles t, t+stride, ...; the centralized producer's
//   issue(g+4) automatically prefills the NEXT tile's 4-stage prologue during
//   this tile's last 4 iterations, so next-tile TMA overlaps the epilogue and
//   there are no per-wave launch/prologue gaps. Ring slot of g+4 == slot of g
//   (STAGES divides KIT), and parity tracking is continuous (KIT % STAGES==0).
// ============================================================================
__device__ __forceinline__ void issue_stage_at(uint32_t sbase, int slot,
                                               int k0, int m0, int n0,
                                               const CUtensorMap* tA,
                                               const CUtensorMap* tB) {
    uint32_t full = sbase + SOFF_FULL + 8 * slot;
    MBARRIER_EXPECT_TX(full, STAGE_BYTES);
    uint32_t st = sbase + SOFF_TILE + slot * STAGE_BYTES;
    TMA_LOAD_2D(st,                tA, k0, m0, full);
    TMA_LOAD_2D(st + A_TILE_BYTES, tB, k0, n0, full);
}

__global__ void __launch_bounds__(NTHREADS, 1)
f16_gemm_kernel(const __grid_constant__ CUtensorMap tmA,
                const __grid_constant__ CUtensorMap tmB,
                const float* __restrict__ bias,
                const float* __restrict__ in_scale,
                const float* __restrict__ w_scale,
                float* __restrict__ out,
                int stride) {
    extern __shared__ __align__(1024) unsigned char smem[];
    const uint32_t sbase = smem_u32(smem);
    const int tid = threadIdx.x;
    const int wid = tid >> 5;
    const int lane = tid & 31;
    const int gid = lane >> 2;   // group id 0..7 (fragment row-in-8)
    const int tig = lane & 3;    // thread-in-group
    const int warp_m = (wid & 1) * 64;    // 2 warps along M
    const int warp_n = (wid >> 1) * 64;   // 4 warps along N

    if (tid == 0) {
        #pragma unroll
        for (int s = 0; s < STAGES; s++) {
            MBARRIER_INIT(sbase + SOFF_FULL + 8 * s, 1);
            MBARRIER_INIT(sbase + SOFF_EMPTY + 8 * s, NWARPS);
        }
    }
    __syncthreads();  // barriers visible before any wait / TMA

    // Prologue for the FIRST tile only; subsequent tiles are prefilled by
    // the in-loop producer during the previous tile's last 4 iterations.
    int t0 = blockIdx.x;
    if (tid == 0 && t0 < NTILES) {
        const int m0 = (t0 / NT_X) * BM;
        const int n0 = (t0 % NT_X) * BN;
        #pragma unroll
        for (int s = 0; s < STAGES; s++)
            issue_stage_at(sbase, s, s * BK, m0, n0, &tmA, &tmB);
    }

    // SW128 swizzle term for our rows is ((row&7)<<4) = gid<<4, constant per
    // thread. k16 step = 32 bytes.
    const uint32_t sx = (uint32_t)gid << 4;
    uint32_t co[4][2];
    #pragma unroll
    for (int s4 = 0; s4 < 4; s4++) {
        #pragma unroll
        for (int h = 0; h < 2; h++)
            co[s4][h] = ((uint32_t)(s4 * 32 + h * 16 + tig * 4)) ^ sx;
    }
    const uint32_t baseA0 = (uint32_t)(warp_m + gid) * 128;
    const uint32_t baseB0 = (uint32_t)(warp_n + gid) * 128 + A_TILE_BYTES;

    const float sc = __ldg(in_scale) * __ldg(w_scale);

    int s = 0, ph = 0;   // continuous ring position across ALL tiles
    for (int t = t0; t < NTILES; t += stride) {
        const int m0 = (t / NT_X) * BM;
        const int n0 = (t % NT_X) * BN;

        float acc[4][8][4];
        #pragma unroll
        for (int i = 0; i < 4; i++)
            #pragma unroll
            for (int j = 0; j < 8; j++)
                #pragma unroll
                for (int q = 0; q < 4; q++) acc[i][j][q] = 0.f;

        for (int it = 0; it < KIT; ++it) {
            MBARRIER_WAIT_PARITY(sbase + SOFF_FULL + 8 * s, ph);

            const uint32_t stg = sbase + SOFF_TILE + (uint32_t)s * STAGE_BYTES;
            const uint32_t aBase = stg + baseA0;
            const uint32_t bBase = stg + baseB0;
            #pragma unroll
            for (int s4 = 0; s4 < 4; s4++) {  // 4 x k16 per BK=64 stage
                uint32_t Af[4][4];
                #pragma unroll
                for (int fm = 0; fm < 4; fm++) {
                    const uint32_t a0 = aBase + fm * 2048 + co[s4][0];
                    const uint32_t a1 = aBase + fm * 2048 + co[s4][1];
                    Af[fm][0] = lds32(a0);
                    Af[fm][1] = lds32(a0 + 1024);
                    Af[fm][2] = lds32(a1);
                    Af[fm][3] = lds32(a1 + 1024);
                }
                uint32_t Bf[8][2];
                #pragma unroll
                for (int fn = 0; fn < 8; fn++) {
                    const uint32_t b0 = bBase + fn * 1024;
                    Bf[fn][0] = lds32(b0 + co[s4][0]);
                    Bf[fn][1] = lds32(b0 + co[s4][1]);
                }
                #pragma unroll
                for (int fn = 0; fn < 8; fn++)
                    #pragma unroll
                    for (int fm = 0; fm < 4; fm++)
                        mma_f16(acc[fm][fn], Af[fm], Bf[fn]);
            }

            // This warp is done reading the ring slot.
            if (lane == 0) MBARRIER_ARRIVE(sbase + SOFF_EMPTY + 8 * s);

            // Centralized producer (R10 style, best measured): refill this
            // slot for global iteration g+4 — either k+4 of this tile, or
            // k' = it+4-KIT of the NEXT tile (prefills its prologue during
            // this tile's last 4 iterations / epilogue).
            if (tid == 0) {
                int git = it + STAGES;
                int im0 = m0, in0 = n0, ik;
                bool ok = true;
                if (git < KIT) {
                    ik = git * BK;
                } else {
                    int t2 = t + stride;
                    ok = (t2 < NTILES);
                    if (ok) {
                        im0 = (t2 / NT_X) * BM;
                        in0 = (t2 % NT_X) * BN;
                        ik = (git - KIT) * BK;
                    }
                }
                if (ok) {
                    MBARRIER_WAIT_PARITY(sbase + SOFF_EMPTY + 8 * s, ph);
                    issue_stage_at(sbase, s, ik, im0, in0, &tmA, &tmB);
                }
            }

            if (++s == STAGES) { s = 0; ph ^= 1; }
        }

        // Epilogue for tile t: scale + bias, float2 stores. Next tile's TMA
        // is already in flight (issued during it=60..63 above).
        #pragma unroll
        for (int fm = 0; fm < 4; fm++) {
            const int r0 = m0 + warp_m + fm * 16 + gid;
            #pragma unroll
            for (int fn = 0; fn < 8; fn++) {
                const int col = n0 + warp_n + fn * 8 + 2 * tig;
                const float2 bv = *reinterpret_cast<const float2*>(bias + col);
                float2 o0, o1;
                o0.x = fmaf(acc[fm][fn][0], sc, bv.x);
                o0.y = fmaf(acc[fm][fn][1], sc, bv.y);
                o1.x = fmaf(acc[fm][fn][2], sc, bv.x);
                o1.y = fmaf(acc[fm][fn][3], sc, bv.y);
                *reinterpret_cast<float2*>(out + (size_t)r0 * N_DIM + col) = o0;
                *reinterpret_cast<float2*>(out + (size_t)(r0 + 8) * N_DIM + col) = o1;
            }
        }
    }
}

// ============================================================================
// Host launch
// ============================================================================
typedef CUresult (CUDAAPI* PFN_encodeTiled)(
    CUtensorMap*, CUtensorMapDataType, cuuint32_t, void*,
    const cuuint64_t*, const cuuint64_t*, const cuuint32_t*, const cuuint32_t*,
    CUtensorMapInterleave, CUtensorMapSwizzle, CUtensorMapL2promotion,
    CUtensorMapFloatOOBfill);

extern "C" void kernel_launch(void* const* d_in, const int* in_sizes, int n_in,
                              void* d_out, int out_size) {
    const float* x      = (const float*)d_in[0];
    const float* w      = (const float*)d_in[1];
    const float* wscale = (const float*)d_in[2];
    const float* bias   = (const float*)d_in[3];
    const float* iscale = (const float*)d_in[4];
    float* out = (float*)d_out;
    (void)in_sizes; (void)n_in; (void)out_size;

    void* qx_p = nullptr; void* qw_p = nullptr;
    cudaGetSymbolAddress(&qx_p, g_qx);
    cudaGetSymbolAddress(&qw_p, g_qw);

    // --- fused quantization to f16-on-e4m3-grid ---
    quant_fused_kernel<<<QX_BLOCKS + QW_BLOCKS, 256>>>(
        (const float4*)x, (const float4*)w,
        (uint32_t*)qx_p, (uint32_t*)qw_p, iscale);

    // --- TMA descriptors (driver entry point via cudart; no -lcuda needed) ---
    PFN_encodeTiled encode = nullptr;
    cudaDriverEntryPointQueryResult qr;
    cudaGetDriverEntryPoint("cuTensorMapEncodeTiled", (void**)&encode,
                            cudaEnableDefault, &qr);

    CUtensorMap tmA, tmB;
    {
        cuuint64_t dims[2]    = {K_DIM, M_DIM};       // elems
        cuuint64_t strides[1] = {K_DIM * 2};          // bytes
        cuuint32_t box[2]     = {BK, BM};             // 64 f16 = 128B (SW128)
        cuuint32_t es[2]      = {1, 1};
        encode(&tmA, CU_TENSOR_MAP_DATA_TYPE_FLOAT16, 2, qx_p, dims, strides,
               box, es, CU_TENSOR_MAP_INTERLEAVE_NONE, CU_TENSOR_MAP_SWIZZLE_128B,
               CU_TENSOR_MAP_L2_PROMOTION_L2_128B, CU_TENSOR_MAP_FLOAT_OOB_FILL_NONE);
    }
    {
        cuuint64_t dims[2]    = {K_DIM, N_DIM};
        cuuint64_t strides[1] = {K_DIM * 2};
        cuuint32_t box[2]     = {BK, BN};             // 64 x 256 box
        cuuint32_t es[2]      = {1, 1};
        encode(&tmB, CU_TENSOR_MAP_DATA_TYPE_FLOAT16, 2, qw_p, dims, strides,
               box, es, CU_TENSOR_MAP_INTERLEAVE_NONE, CU_TENSOR_MAP_SWIZZLE_128B,
               CU_TENSOR_MAP_L2_PROMOTION_L2_128B, CU_TENSOR_MAP_FLOAT_OOB_FILL_NONE);
    }

    // Persistent grid: one CTA per SM (1 CTA/SM due to 193KB smem).
    int nsm = 148;
    cudaDeviceGetAttribute(&nsm, cudaDevAttrMultiProcessorCount, 0);
    if (nsm > NTILES) nsm = NTILES;

    cudaFuncSetAttribute(f16_gemm_kernel,
                         cudaFuncAttributeMaxDynamicSharedMemorySize, SMEM_TOTAL);
    f16_gemm_kernel<<<nsm, NTHREADS, SMEM_TOTAL>>>(
        tmA, tmB, bias, iscale, wscale, out, nsm);
}